// round 12
// baseline (speedup 1.0000x reference)
#include <cuda_runtime.h>
#include <cuda_fp16.h>
#include <cstdint>

// ====================== device scratch (no allocs allowed) ======================
__device__ unsigned g_amax_bits;                        // bit pattern of max|W| (monotone, idempotent across replays)
// B fragments for mma.m16n8k16 (B = hi/lo f16 split of A), packed layout:
// [kstep 0..255][t 0..3][lane 0..31] -> uint4 { hi_t.b0, hi_t.b1, lo_t.b0, lo_t.b1 }
__device__ __align__(16) uint4 g_Bfrag4[256 * 4 * 32];  // 512 KB (L2-resident, L1-shared)

// ====================== constants ======================
static constexpr int K_DIM  = 4096;
static constexpr int N_OUT  = 12288;
static constexpr int MTILE  = 16;                  // W rows per CTA (1 rowtile)
static constexpr int NTILES = N_OUT / MTILE;       // 768
static constexpr int KSPLIT = 8;                   // K-groups (one warp each)
static constexpr int KS_GRP = 256 / KSPLIT;        // 32 ksteps per group (512 k)

// ====================== helpers ======================
// quantize-dequant pair -> f16x2 of e4m3(RN-sat(w*scale)); lo half = a, hi half = b.
static __device__ __forceinline__ uint32_t qd_pair(float a, float b, float scale) {
    float as = __fmul_rn(a, scale);
    float bs = __fmul_rn(b, scale);
    unsigned short p;
    asm("cvt.rn.satfinite.e4m3x2.f32 %0, %1, %2;" : "=h"(p) : "f"(bs), "f"(as));
    uint32_t r;
    asm("cvt.rn.f16x2.e4m3x2 %0, %1;" : "=r"(r) : "h"(p));
    return r;
}

static __device__ __forceinline__ void mma16816(float* d,
    uint32_t a0, uint32_t a1, uint32_t a2, uint32_t a3, uint32_t b0, uint32_t b1) {
    asm volatile(
        "mma.sync.aligned.m16n8k16.row.col.f32.f16.f16.f32 "
        "{%0,%1,%2,%3}, {%4,%5,%6,%7}, {%8,%9}, {%0,%1,%2,%3};"
        : "+f"(d[0]), "+f"(d[1]), "+f"(d[2]), "+f"(d[3])
        : "r"(a0), "r"(a1), "r"(a2), "r"(a3), "r"(b0), "r"(b1));
}

// ====================== kernel 1: amax over |W| (+ B-fragment prep in blocks < 128) ======================
__global__ void __launch_bounds__(256) k_amax(const float* __restrict__ W,
                                              const float* __restrict__ A) {
    if (blockIdx.x < 128) {
        const int idx  = blockIdx.x * 256 + threadIdx.x;   // [ks 0..255][t 0..3][lane 0..31]
        const int lane = idx & 31;
        const int t    = (idx >> 5) & 3;
        const int ks   = idx >> 7;
        const int r    = 8 * t + (lane >> 2);
        const int c    = lane & 3;
        const int k    = ks * 16;

        const float* Ar = A + (size_t)r * K_DIM;
        float2 p0 = *(const float2*)(Ar + k + 2 * c);
        float2 p1 = *(const float2*)(Ar + k + 8 + 2 * c);

        __half h0x = __float2half_rn(p0.x), h0y = __float2half_rn(p0.y);
        __half h1x = __float2half_rn(p1.x), h1y = __float2half_rn(p1.y);
        __half l0x = __float2half_rn(p0.x - __half2float(h0x));
        __half l0y = __float2half_rn(p0.y - __half2float(h0y));
        __half l1x = __float2half_rn(p1.x - __half2float(h1x));
        __half l1y = __float2half_rn(p1.y - __half2float(h1y));

        uint4 v;
        v.x = (uint32_t)__half_as_ushort(h0x) | ((uint32_t)__half_as_ushort(h0y) << 16);
        v.y = (uint32_t)__half_as_ushort(h1x) | ((uint32_t)__half_as_ushort(h1y) << 16);
        v.z = (uint32_t)__half_as_ushort(l0x) | ((uint32_t)__half_as_ushort(l0y) << 16);
        v.w = (uint32_t)__half_as_ushort(l1x) | ((uint32_t)__half_as_ushort(l1y) << 16);
        g_Bfrag4[idx] = v;
    }

    __shared__ float red[8];
    const float4* W4 = (const float4*)W;
    const int n4 = (N_OUT * K_DIM) / 4;
    float m0 = 0.f, m1 = 0.f, m2 = 0.f, m3 = 0.f;
    const int stride = gridDim.x * blockDim.x;
    #pragma unroll 4
    for (int i = blockIdx.x * blockDim.x + threadIdx.x; i < n4; i += stride) {
        float4 v = W4[i];
        m0 = fmaxf(m0, fabsf(v.x));
        m1 = fmaxf(m1, fabsf(v.y));
        m2 = fmaxf(m2, fabsf(v.z));
        m3 = fmaxf(m3, fabsf(v.w));
    }
    float m = fmaxf(fmaxf(m0, m1), fmaxf(m2, m3));
    #pragma unroll
    for (int o = 16; o; o >>= 1) m = fmaxf(m, __shfl_xor_sync(0xFFFFFFFFu, m, o));
    if ((threadIdx.x & 31) == 0) red[threadIdx.x >> 5] = m;
    __syncthreads();
    if (threadIdx.x == 0) {
        float b = red[0];
        #pragma unroll
        for (int i = 1; i < 8; ++i) b = fmaxf(b, red[i]);
        atomicMax(&g_amax_bits, __float_as_uint(b));
    }
}

// ====================== kernel 2: fused quantize + GEMM, K-split x8, no B smem ======================
// 768 CTAs x 256 threads, 4 resident CTAs/SM (~32 warps/SM). CTA: 16 W rows x full K.
// Warp w = K-group (k in [512w, 512w+512)); warps fully independent until epilogue.
__global__ void __launch_bounds__(256, 4) k_gemm(const float* __restrict__ W,
                                                 const float* __restrict__ bias,
                                                 float* __restrict__ out) {
    __shared__ float red[KSPLIT][4][4][32];         // 16 KB, epilogue only

    const int tid  = threadIdx.x;
    const int lane = tid & 31;
    const int w    = tid >> 5;                      // K-group 0..7
    const int nb   = (NTILES - 1 - blockIdx.x) * MTILE;   // reversed tile order (L2 reuse)

    const float amax  = fmaxf(__uint_as_float(g_amax_bits), 1e-12f);
    const float scale = __fdiv_rn(448.0f, amax);

    // ---- W pointers: LDG.128 per lane, permuted k offset ----
    const int c    = lane & 3;
    const int perm = 8 * (c & 1) + 4 * (c >> 1);    // {0,8,4,12}
    const bool codd = (c & 1);
    const float* p0 = W + (size_t)(nb + (lane >> 2)) * K_DIM + 512 * w + perm;
    const float* p1 = p0 + 8 * K_DIM;

    // ---- W register pipeline: 4 kstep stages x 2 float4 ----
    float4 sA[4], sB[4];
    #pragma unroll
    for (int s = 0; s < 4; ++s) {
        sA[s] = *(const float4*)(p0 + 16 * s);
        sB[s] = *(const float4*)(p1 + 16 * s);
    }

    // ---- B fragment base for this group (direct L2/L1 reads) ----
    const uint4* bbase = g_Bfrag4 + (size_t)(w * KS_GRP) * 4 * 32 + lane;

    float acc[4][4];
    #pragma unroll
    for (int t = 0; t < 4; ++t)
        #pragma unroll
        for (int i = 0; i < 4; ++i) acc[t][i] = 0.f;

    #pragma unroll 4
    for (int ks = 0; ks < KS_GRP; ++ks) {
        const int s = ks & 3;
        // quantize stage s -> two f16x2 per row, then shuffle-exchange
        uint32_t u0r = qd_pair(sA[s].x, sA[s].y, scale);
        uint32_t u1r = qd_pair(sA[s].z, sA[s].w, scale);
        uint32_t u0q = qd_pair(sB[s].x, sB[s].y, scale);
        uint32_t u1q = qd_pair(sB[s].z, sB[s].w, scale);
        uint32_t rr = __shfl_xor_sync(0xFFFFFFFFu, codd ? u0r : u1r, 1);
        uint32_t rq = __shfl_xor_sync(0xFFFFFFFFu, codd ? u0q : u1q, 1);
        uint32_t a0 = codd ? rr  : u0r;
        uint32_t a2 = codd ? u1r : rr;
        uint32_t a1 = codd ? rq  : u0q;
        uint32_t a3 = codd ? u1q : rq;
        // reload stage with kstep 4 ahead (clamped; tail reloads are redundant L1 hits)
        int ksn = ks + 4;
        ksn = ksn > KS_GRP - 1 ? KS_GRP - 1 : ksn;
        sA[s] = *(const float4*)(p0 + 16 * ksn);
        sB[s] = *(const float4*)(p1 + 16 * ksn);
        // B direct loads + MMAs (hi t and lo t+4 share the accumulator)
        const uint4* bp = bbase + (size_t)ks * 4 * 32;
        #pragma unroll
        for (int t = 0; t < 4; ++t) {
            uint4 b = __ldg(bp + t * 32);
            mma16816(acc[t], a0, a1, a2, a3, b.x, b.y);   // hi
            mma16816(acc[t], a0, a1, a2, a3, b.z, b.w);   // lo (same out cols)
        }
    }

    // ---- cross-group reduction via smem ----
    #pragma unroll
    for (int t = 0; t < 4; ++t)
        #pragma unroll
        for (int i = 0; i < 4; ++i)
            red[w][t][i][lane] = acc[t][i];
    __syncthreads();

    // ---- coalesced epilogue: thread -> (A-row ar, 2 consecutive cols) ----
    const float recip = __frcp_rn(scale);
    const int ar = tid >> 3;                        // 0..31
    const int c0 = (tid & 7) * 2;                   // 0..14
    float v[2];
    #pragma unroll
    for (int cc = 0; cc < 2; ++cc) {
        const int col = c0 + cc;                    // 0..15
        const int ln  = (col & 7) * 4 + ((ar >> 1) & 3);
        const int i2  = (ar & 1) + 2 * (col >> 3);
        const int t2  = ar >> 3;
        float s = 0.f;
        #pragma unroll
        for (int g2 = 0; g2 < KSPLIT; ++g2) s += red[g2][t2][i2][ln];
        v[cc] = s * recip + bias[nb + col];
    }
    *(float2*)(out + (size_t)ar * N_OUT + nb + c0) = make_float2(v[0], v[1]);
}

// ====================== launch ======================
extern "C" void kernel_launch(void* const* d_in, const int* in_sizes, int n_in,
                              void* d_out, int out_size) {
    const float* A    = (const float*)d_in[0];   // [32, 4096]
    const float* W    = (const float*)d_in[1];   // [12288, 4096]
    const float* bias = (const float*)d_in[2];   // [12288]
    float* out        = (float*)d_out;           // [32, 12288]

    k_amax<<<1184, 256>>>(W, A);
    k_gemm<<<NTILES, 256>>>(W, bias, out);
}

// round 13
// speedup vs baseline: 1.4821x; 1.4821x over previous
#include <cuda_runtime.h>
#include <cuda_fp16.h>
#include <cstdint>

// ====================== device scratch (no allocs allowed) ======================
__device__ unsigned g_amax_bits;                        // bit pattern of max|W| (monotone, idempotent across replays)
// B fragments for mma.m16n8k16 (B = f16(A)), fragment layout:
// [kstep 0..255][t 0..3][lane 0..31] -> uint2 { b0, b1 },  rows n = 8t + (lane>>2)
__device__ __align__(16) uint2 g_Bfrag2[256 * 4 * 32];  // 256 KB (L2-resident)

// ====================== constants ======================
static constexpr int K_DIM  = 4096;
static constexpr int N_OUT  = 12288;
static constexpr int MTILE  = 32;                  // W rows per CTA (2 rowtiles x 16)
static constexpr int NTILES = N_OUT / MTILE;       // 384
static constexpr int KS_PER_SLAB = 8;              // ksteps per B slab
static constexpr int BSLAB  = KS_PER_SLAB * 4 * 32 * 8;   // 8 KB
static constexpr int KS_GRP = 64;                  // ksteps per K-quarter group (1024 k)
static constexpr int NSLABS = KS_GRP / KS_PER_SLAB;       // 8 slabs per group
static constexpr int DSMEM  = 8 * BSLAB;           // 64 KB: 4 groups x double buffer

// ====================== helpers ======================
static __device__ __forceinline__ uint32_t smem_u32(const void* p) {
    uint32_t a;
    asm("{ .reg .u64 t; cvta.to.shared.u64 t, %1; cvt.u32.u64 %0, t; }" : "=r"(a) : "l"(p));
    return a;
}
#define CP_ASYNC16(dst, src) \
    asm volatile("cp.async.cg.shared.global [%0], [%1], 16;" :: "r"(dst), "l"(src))
#define CP_COMMIT() asm volatile("cp.async.commit_group;" ::: "memory")
#define CP_WAIT(n)  asm volatile("cp.async.wait_group %0;" :: "n"(n) : "memory")
#define BAR_SYNC64(id) asm volatile("bar.sync %0, 64;" :: "r"(id) : "memory")

// streaming (evict-first) float4 load
static __device__ __forceinline__ float4 ldcs_f4(const float* p) {
    float4 v;
    asm volatile("ld.global.cs.v4.f32 {%0, %1, %2, %3}, [%4];"
                 : "=f"(v.x), "=f"(v.y), "=f"(v.z), "=f"(v.w) : "l"(p));
    return v;
}

// quantize-dequant pair -> f16x2 of e4m3(RN-sat(w*scale)); lo half = a, hi half = b.
static __device__ __forceinline__ uint32_t qd_pair(float a, float b, float scale) {
    float as = __fmul_rn(a, scale);
    float bs = __fmul_rn(b, scale);
    unsigned short p;
    asm("cvt.rn.satfinite.e4m3x2.f32 %0, %1, %2;" : "=h"(p) : "f"(bs), "f"(as));
    uint32_t r;
    asm("cvt.rn.f16x2.e4m3x2 %0, %1;" : "=r"(r) : "h"(p));
    return r;
}

static __device__ __forceinline__ void mma16816(float* d,
    uint32_t a0, uint32_t a1, uint32_t a2, uint32_t a3, uint32_t b0, uint32_t b1) {
    asm volatile(
        "mma.sync.aligned.m16n8k16.row.col.f32.f16.f16.f32 "
        "{%0,%1,%2,%3}, {%4,%5,%6,%7}, {%8,%9}, {%0,%1,%2,%3};"
        : "+f"(d[0]), "+f"(d[1]), "+f"(d[2]), "+f"(d[3])
        : "r"(a0), "r"(a1), "r"(a2), "r"(a3), "r"(b0), "r"(b1));
}

// ====================== kernel 1: amax over |W| (+ B-fragment prep in blocks < 128) ======================
__global__ void __launch_bounds__(256) k_amax(const float* __restrict__ W,
                                              const float* __restrict__ A) {
    if (blockIdx.x < 128) {
        const int idx  = blockIdx.x * 256 + threadIdx.x;   // [ks 0..255][t 0..3][lane 0..31]
        const int lane = idx & 31;
        const int t    = (idx >> 5) & 3;
        const int ks   = idx >> 7;
        const int r    = 8 * t + (lane >> 2);
        const int c    = lane & 3;
        const int k    = ks * 16;

        const float* Ar = A + (size_t)r * K_DIM;
        float2 p0 = *(const float2*)(Ar + k + 2 * c);
        float2 p1 = *(const float2*)(Ar + k + 8 + 2 * c);

        uint32_t b0 = (uint32_t)__half_as_ushort(__float2half_rn(p0.x))
                    | ((uint32_t)__half_as_ushort(__float2half_rn(p0.y)) << 16);
        uint32_t b1 = (uint32_t)__half_as_ushort(__float2half_rn(p1.x))
                    | ((uint32_t)__half_as_ushort(__float2half_rn(p1.y)) << 16);
        g_Bfrag2[idx] = make_uint2(b0, b1);
    }

    __shared__ float red[8];
    const float4* W4 = (const float4*)W;
    const int n4 = (N_OUT * K_DIM) / 4;
    float m0 = 0.f, m1 = 0.f, m2 = 0.f, m3 = 0.f;
    const int stride = gridDim.x * blockDim.x;
    #pragma unroll 4
    for (int i = blockIdx.x * blockDim.x + threadIdx.x; i < n4; i += stride) {
        float4 v = W4[i];
        m0 = fmaxf(m0, fabsf(v.x));
        m1 = fmaxf(m1, fabsf(v.y));
        m2 = fmaxf(m2, fabsf(v.z));
        m3 = fmaxf(m3, fabsf(v.w));
    }
    float m = fmaxf(fmaxf(m0, m1), fmaxf(m2, m3));
    #pragma unroll
    for (int o = 16; o; o >>= 1) m = fmaxf(m, __shfl_xor_sync(0xFFFFFFFFu, m, o));
    if ((threadIdx.x & 31) == 0) red[threadIdx.x >> 5] = m;
    __syncthreads();
    if (threadIdx.x == 0) {
        float b = red[0];
        #pragma unroll
        for (int i = 1; i < 8; ++i) b = fmaxf(b, red[i]);
        atomicMax(&g_amax_bits, __float_as_uint(b));
    }
}

// ====================== kernel 2: fused quantize + GEMM, K-split x4, single f16 A term ======================
// 384 CTAs x 256 threads. CTA: 32 W rows x full K.
// Warp w: rowtile lw=w&1 (16 rows), K-quarter g=w>>1 (k in [1024g, 1024g+1024)).
__global__ void __launch_bounds__(256) k_gemm(const float* __restrict__ W,
                                              const float* __restrict__ bias,
                                              float* __restrict__ out) {
    extern __shared__ __align__(16) char bbuf[];    // [group][buf][BSLAB] = 64 KB

    const int tid  = threadIdx.x;
    const int lane = tid & 31;
    const int wid  = tid >> 5;
    const int g    = wid >> 1;                      // K-quarter group 0..3
    const int lw   = wid & 1;                       // rowtile
    const int tig  = tid & 63;                      // thread in group
    const int nb   = (NTILES - 1 - blockIdx.x) * MTILE;   // reversed tile order (L2 reuse)

    const float amax  = fmaxf(__uint_as_float(g_amax_bits), 1e-12f);
    const float scale = __fdiv_rn(448.0f, amax);

    // ---- W pointers: LDG.128 per lane, permuted k offset ----
    const int c    = lane & 3;
    const int perm = 8 * (c & 1) + 4 * (c >> 1);    // {0,8,4,12}
    const bool codd = (c & 1);
    const float* p0 = W + (size_t)(nb + 16 * lw + (lane >> 2)) * K_DIM + 1024 * g + perm;
    const float* p1 = p0 + 8 * K_DIM;

    // ---- W register pipeline: 4 kstep stages x 2 float4 ----
    float4 sA[4], sB[4];
    #pragma unroll
    for (int s = 0; s < 4; ++s) {
        sA[s] = ldcs_f4(p0 + 16 * s);
        sB[s] = ldcs_f4(p1 + 16 * s);
    }

    // ---- per-group B double buffer (8 KB slabs of 8 ksteps) ----
    char* myb0 = bbuf + (size_t)(2 * g) * BSLAB;
    char* myb1 = myb0 + BSLAB;
    const char* bsrc = (const char*)g_Bfrag2 + (size_t)g * (NSLABS * BSLAB);
    {
        uint32_t bd = smem_u32(myb0) + tig * 16;
        #pragma unroll
        for (int i = 0; i < 8; ++i) CP_ASYNC16(bd + i * 1024, bsrc + tig * 16 + i * 1024);
        CP_COMMIT();
    }

    float acc[4][4];
    #pragma unroll
    for (int t = 0; t < 4; ++t)
        #pragma unroll
        for (int i = 0; i < 4; ++i) acc[t][i] = 0.f;

    for (int lc = 0; lc < NSLABS; ++lc) {           // 8 local slabs (8 ksteps each)
        if (lc + 1 < NSLABS) {
            uint32_t bd = smem_u32((lc + 1) & 1 ? myb1 : myb0) + tig * 16;
            const char* bs = bsrc + (size_t)(lc + 1) * BSLAB + tig * 16;
            #pragma unroll
            for (int i = 0; i < 8; ++i) CP_ASYNC16(bd + i * 1024, bs + i * 1024);
            CP_COMMIT();
            CP_WAIT(1);
        } else {
            CP_WAIT(0);
        }
        BAR_SYNC64(g + 1);                          // slab lc visible to group

        const char* bb = (lc & 1) ? myb1 : myb0;
        #pragma unroll
        for (int j = 0; j < KS_PER_SLAB; ++j) {
            const int s = j & 3;
            // quantize stage s -> two f16x2 per row, then shuffle-exchange
            uint32_t u0r = qd_pair(sA[s].x, sA[s].y, scale);
            uint32_t u1r = qd_pair(sA[s].z, sA[s].w, scale);
            uint32_t u0q = qd_pair(sB[s].x, sB[s].y, scale);
            uint32_t u1q = qd_pair(sB[s].z, sB[s].w, scale);
            uint32_t rr = __shfl_xor_sync(0xFFFFFFFFu, codd ? u0r : u1r, 1);
            uint32_t rq = __shfl_xor_sync(0xFFFFFFFFu, codd ? u0q : u1q, 1);
            uint32_t a0 = codd ? rr  : u0r;
            uint32_t a2 = codd ? u1r : rr;
            uint32_t a1 = codd ? rq  : u0q;
            uint32_t a3 = codd ? u1q : rq;
            // reload stage with kstep 4 ahead (clamped; tail loads are redundant)
            int ksn = lc * KS_PER_SLAB + j + 4;
            ksn = ksn > KS_GRP - 1 ? KS_GRP - 1 : ksn;
            sA[s] = ldcs_f4(p0 + 16 * ksn);
            sB[s] = ldcs_f4(p1 + 16 * ksn);
            #pragma unroll
            for (int t = 0; t < 4; ++t) {
                uint2 b = *(const uint2*)(bb + ((j * 4 + t) * 32 + lane) * 8);
                mma16816(acc[t], a0, a1, a2, a3, b.x, b.y);
            }
        }
        BAR_SYNC64(g + 1);                          // group done with slab lc
    }

    // ---- cross-group reduction via smem (reuse bbuf; 16 KB) ----
    __syncthreads();
    float* red = (float*)bbuf;                      // [g][lw][t][i][lane]
    #pragma unroll
    for (int t = 0; t < 4; ++t)
        #pragma unroll
        for (int i = 0; i < 4; ++i)
            red[(((g * 2 + lw) * 4 + t) * 4 + i) * 32 + lane] = acc[t][i];
    __syncthreads();

    // ---- coalesced epilogue: thread -> (A-row ar, 4 consecutive cols) ----
    const float recip = __frcp_rn(scale);
    const int ar = tid >> 3;                        // 0..31
    const int c0 = (tid & 7) * 4;                   // 0..28
    float v[4];
    #pragma unroll
    for (int cc = 0; cc < 4; ++cc) {
        const int col = c0 + cc;
        const int lw2 = col >> 4;
        const int lr  = col & 15;
        const int ln2 = (lr & 7) * 4 + ((ar >> 1) & 3);
        const int i2  = (ar & 1) + 2 * (lr >> 3);
        const int t2  = ar >> 3;
        float s = 0.f;
        #pragma unroll
        for (int g2 = 0; g2 < 4; ++g2)
            s += red[(((g2 * 2 + lw2) * 4 + t2) * 4 + i2) * 32 + ln2];
        v[cc] = s * recip + bias[nb + col];
    }
    *(float4*)(out + (size_t)ar * N_OUT + nb + c0) = make_float4(v[0], v[1], v[2], v[3]);
}

// ====================== launch ======================
extern "C" void kernel_launch(void* const* d_in, const int* in_sizes, int n_in,
                              void* d_out, int out_size) {
    const float* A    = (const float*)d_in[0];   // [32, 4096]
    const float* W    = (const float*)d_in[1];   // [12288, 4096]
    const float* bias = (const float*)d_in[2];   // [12288]
    float* out        = (float*)d_out;           // [32, 12288]

    cudaFuncSetAttribute(k_gemm, cudaFuncAttributeMaxDynamicSharedMemorySize, DSMEM);

    k_amax<<<1184, 256>>>(W, A);
    k_gemm<<<NTILES, 256, DSMEM>>>(W, bias, out);
}

// round 14
// speedup vs baseline: 1.4880x; 1.0040x over previous
#include <cuda_runtime.h>
#include <cuda_fp16.h>
#include <cstdint>

// ====================== device scratch (no allocs allowed) ======================
__device__ unsigned g_amax_bits;                        // bit pattern of max|W| (monotone, idempotent across replays)
// B fragments for mma.m16n8k16 (B = f16(A)), t-PAIR packed layout:
// [kstep 0..255][tp 0..1][lane 0..31] -> uint4 { t.b0, t.b1, (t+1).b0, (t+1).b1 }, t = 2*tp
//   rows for t: n = 8t + (lane>>2)
__device__ __align__(16) uint4 g_BfragP[256 * 2 * 32];  // 256 KB (L2-resident)

// ====================== constants ======================
static constexpr int K_DIM  = 4096;
static constexpr int N_OUT  = 12288;
static constexpr int MTILE  = 32;                  // W rows per CTA (2 rowtiles x 16)
static constexpr int NTILES = N_OUT / MTILE;       // 384
static constexpr int KS_PER_SLAB = 8;              // ksteps per B slab
static constexpr int BSLAB  = KS_PER_SLAB * 2 * 32 * 16;  // 8 KB
static constexpr int KS_GRP = 64;                  // ksteps per K-quarter group (1024 k)
static constexpr int NSLABS = KS_GRP / KS_PER_SLAB;       // 8 slabs per group
static constexpr int DSMEM  = 8 * BSLAB;           // 64 KB: 4 groups x double buffer

// ====================== helpers ======================
static __device__ __forceinline__ uint32_t smem_u32(const void* p) {
    uint32_t a;
    asm("{ .reg .u64 t; cvta.to.shared.u64 t, %1; cvt.u32.u64 %0, t; }" : "=r"(a) : "l"(p));
    return a;
}
#define CP_ASYNC16(dst, src) \
    asm volatile("cp.async.cg.shared.global [%0], [%1], 16;" :: "r"(dst), "l"(src))
#define CP_COMMIT() asm volatile("cp.async.commit_group;" ::: "memory")
#define CP_WAIT(n)  asm volatile("cp.async.wait_group %0;" :: "n"(n) : "memory")
#define BAR_SYNC64(id) asm volatile("bar.sync %0, 64;" :: "r"(id) : "memory")

// quantize-dequant pair -> f16x2 of e4m3(RN-sat(w*scale)); lo half = a, hi half = b.
static __device__ __forceinline__ uint32_t qd_pair(float a, float b, float scale) {
    float as = __fmul_rn(a, scale);
    float bs = __fmul_rn(b, scale);
    unsigned short p;
    asm("cvt.rn.satfinite.e4m3x2.f32 %0, %1, %2;" : "=h"(p) : "f"(bs), "f"(as));
    uint32_t r;
    asm("cvt.rn.f16x2.e4m3x2 %0, %1;" : "=r"(r) : "h"(p));
    return r;
}

static __device__ __forceinline__ void mma16816(float* d,
    uint32_t a0, uint32_t a1, uint32_t a2, uint32_t a3, uint32_t b0, uint32_t b1) {
    asm volatile(
        "mma.sync.aligned.m16n8k16.row.col.f32.f16.f16.f32 "
        "{%0,%1,%2,%3}, {%4,%5,%6,%7}, {%8,%9}, {%0,%1,%2,%3};"
        : "+f"(d[0]), "+f"(d[1]), "+f"(d[2]), "+f"(d[3])
        : "r"(a0), "r"(a1), "r"(a2), "r"(a3), "r"(b0), "r"(b1));
}

// ====================== kernel 1: amax over |W| (+ B-fragment prep in blocks < 64) ======================
__global__ void __launch_bounds__(256) k_amax(const float* __restrict__ W,
                                              const float* __restrict__ A) {
    if (blockIdx.x < 64) {
        const int idx  = blockIdx.x * 256 + threadIdx.x;   // [ks 0..255][tp 0..1][lane 0..31]
        const int lane = idx & 31;
        const int tp   = (idx >> 5) & 1;
        const int ks   = idx >> 6;
        const int r0   = 16 * tp + (lane >> 2);            // rows for t = 2*tp
        const int r1   = r0 + 8;                           // rows for t = 2*tp + 1
        const int c    = lane & 3;
        const int k    = ks * 16;

        const float* Ar0 = A + (size_t)r0 * K_DIM;
        const float* Ar1 = A + (size_t)r1 * K_DIM;
        float2 q00 = *(const float2*)(Ar0 + k + 2 * c);
        float2 q01 = *(const float2*)(Ar0 + k + 8 + 2 * c);
        float2 q10 = *(const float2*)(Ar1 + k + 2 * c);
        float2 q11 = *(const float2*)(Ar1 + k + 8 + 2 * c);

        auto pack = [](float2 p) -> uint32_t {
            return (uint32_t)__half_as_ushort(__float2half_rn(p.x))
                 | ((uint32_t)__half_as_ushort(__float2half_rn(p.y)) << 16);
        };
        g_BfragP[idx] = make_uint4(pack(q00), pack(q01), pack(q10), pack(q11));
    }

    __shared__ float red[8];
    const float4* W4 = (const float4*)W;
    const int n4 = (N_OUT * K_DIM) / 4;
    float m0 = 0.f, m1 = 0.f, m2 = 0.f, m3 = 0.f;
    const int stride = gridDim.x * blockDim.x;
    #pragma unroll 4
    for (int i = blockIdx.x * blockDim.x + threadIdx.x; i < n4; i += stride) {
        float4 v = W4[i];
        m0 = fmaxf(m0, fabsf(v.x));
        m1 = fmaxf(m1, fabsf(v.y));
        m2 = fmaxf(m2, fabsf(v.z));
        m3 = fmaxf(m3, fabsf(v.w));
    }
    float m = fmaxf(fmaxf(m0, m1), fmaxf(m2, m3));
    #pragma unroll
    for (int o = 16; o; o >>= 1) m = fmaxf(m, __shfl_xor_sync(0xFFFFFFFFu, m, o));
    if ((threadIdx.x & 31) == 0) red[threadIdx.x >> 5] = m;
    __syncthreads();
    if (threadIdx.x == 0) {
        float b = red[0];
        #pragma unroll
        for (int i = 1; i < 8; ++i) b = fmaxf(b, red[i]);
        atomicMax(&g_amax_bits, __float_as_uint(b));
    }
}

// ====================== kernel 2: fused quantize + GEMM, K-split x4, single f16 A term ======================
// 384 CTAs x 256 threads. CTA: 32 W rows x full K.
// Warp w: rowtile lw=w&1 (16 rows), K-quarter g=w>>1 (k in [1024g, 1024g+1024)).
__global__ void __launch_bounds__(256) k_gemm(const float* __restrict__ W,
                                              const float* __restrict__ bias,
                                              float* __restrict__ out) {
    extern __shared__ __align__(16) char bbuf[];    // [group][buf][BSLAB] = 64 KB

    const int tid  = threadIdx.x;
    const int lane = tid & 31;
    const int wid  = tid >> 5;
    const int g    = wid >> 1;                      // K-quarter group 0..3
    const int lw   = wid & 1;                       // rowtile
    const int tig  = tid & 63;                      // thread in group
    const int nb   = (NTILES - 1 - blockIdx.x) * MTILE;   // reversed tile order (L2 reuse)

    const float amax  = fmaxf(__uint_as_float(g_amax_bits), 1e-12f);
    const float scale = __fdiv_rn(448.0f, amax);

    // ---- W pointers: LDG.128 per lane, permuted k offset ----
    const int c    = lane & 3;
    const int perm = 8 * (c & 1) + 4 * (c >> 1);    // {0,8,4,12}
    const bool codd = (c & 1);
    const float4* p0 = (const float4*)(W + (size_t)(nb + 16 * lw + (lane >> 2)) * K_DIM + 1024 * g + perm);
    const float4* p1 = (const float4*)((const float*)p0 + 8 * K_DIM);

    // ---- W register pipeline: 4 kstep stages x 2 float4 (cached loads; tail stays in L2 for next amax) ----
    float4 sA[4], sB[4];
    #pragma unroll
    for (int s = 0; s < 4; ++s) {
        sA[s] = __ldg(p0 + 4 * s);
        sB[s] = __ldg(p1 + 4 * s);
    }

    // ---- per-group B double buffer (8 KB slabs of 8 ksteps) ----
    char* myb0 = bbuf + (size_t)(2 * g) * BSLAB;
    char* myb1 = myb0 + BSLAB;
    const char* bsrc = (const char*)g_BfragP + (size_t)g * (NSLABS * BSLAB);
    {
        uint32_t bd = smem_u32(myb0) + tig * 16;
        #pragma unroll
        for (int i = 0; i < 8; ++i) CP_ASYNC16(bd + i * 1024, bsrc + tig * 16 + i * 1024);
        CP_COMMIT();
    }

    float acc[4][4];
    #pragma unroll
    for (int t = 0; t < 4; ++t)
        #pragma unroll
        for (int i = 0; i < 4; ++i) acc[t][i] = 0.f;

    for (int lc = 0; lc < NSLABS; ++lc) {           // 8 local slabs (8 ksteps each)
        if (lc + 1 < NSLABS) {
            uint32_t bd = smem_u32((lc + 1) & 1 ? myb1 : myb0) + tig * 16;
            const char* bs = bsrc + (size_t)(lc + 1) * BSLAB + tig * 16;
            #pragma unroll
            for (int i = 0; i < 8; ++i) CP_ASYNC16(bd + i * 1024, bs + i * 1024);
            CP_COMMIT();
            CP_WAIT(1);
        } else {
            CP_WAIT(0);
        }
        BAR_SYNC64(g + 1);                          // slab lc visible to group

        const char* bb = (lc & 1) ? myb1 : myb0;
        #pragma unroll
        for (int j = 0; j < KS_PER_SLAB; ++j) {
            const int s = j & 3;
            // quantize stage s -> two f16x2 per row, then shuffle-exchange
            uint32_t u0r = qd_pair(sA[s].x, sA[s].y, scale);
            uint32_t u1r = qd_pair(sA[s].z, sA[s].w, scale);
            uint32_t u0q = qd_pair(sB[s].x, sB[s].y, scale);
            uint32_t u1q = qd_pair(sB[s].z, sB[s].w, scale);
            uint32_t rr = __shfl_xor_sync(0xFFFFFFFFu, codd ? u0r : u1r, 1);
            uint32_t rq = __shfl_xor_sync(0xFFFFFFFFu, codd ? u0q : u1q, 1);
            uint32_t a0 = codd ? rr  : u0r;
            uint32_t a2 = codd ? u1r : rr;
            uint32_t a1 = codd ? rq  : u0q;
            uint32_t a3 = codd ? u1q : rq;
            // reload stage with kstep 4 ahead (clamped; tail loads are redundant L1/L2 hits)
            int ksn = lc * KS_PER_SLAB + j + 4;
            ksn = ksn > KS_GRP - 1 ? KS_GRP - 1 : ksn;
            sA[s] = __ldg(p0 + 4 * ksn);
            sB[s] = __ldg(p1 + 4 * ksn);
            // B t-pair loads (LDS.128) + MMAs
            #pragma unroll
            for (int tp = 0; tp < 2; ++tp) {
                uint4 b = *(const uint4*)(bb + ((j * 2 + tp) * 32 + lane) * 16);
                mma16816(acc[2 * tp],     a0, a1, a2, a3, b.x, b.y);
                mma16816(acc[2 * tp + 1], a0, a1, a2, a3, b.z, b.w);
            }
        }
        BAR_SYNC64(g + 1);                          // group done with slab lc
    }

    // ---- cross-group reduction via smem (reuse bbuf; 16 KB) ----
    __syncthreads();
    float* red = (float*)bbuf;                      // [g][lw][t][i][lane]
    #pragma unroll
    for (int t = 0; t < 4; ++t)
        #pragma unroll
        for (int i = 0; i < 4; ++i)
            red[(((g * 2 + lw) * 4 + t) * 4 + i) * 32 + lane] = acc[t][i];
    __syncthreads();

    // ---- coalesced epilogue: thread -> (A-row ar, 4 consecutive cols) ----
    const float recip = __frcp_rn(scale);
    const int ar = tid >> 3;                        // 0..31
    const int c0 = (tid & 7) * 4;                   // 0..28
    float v[4];
    #pragma unroll
    for (int cc = 0; cc < 4; ++cc) {
        const int col = c0 + cc;
        const int lw2 = col >> 4;
        const int lr  = col & 15;
        const int ln2 = (lr & 7) * 4 + ((ar >> 1) & 3);
        const int i2  = (ar & 1) + 2 * (lr >> 3);
        const int t2  = ar >> 3;
        float s = 0.f;
        #pragma unroll
        for (int g2 = 0; g2 < 4; ++g2)
            s += red[(((g2 * 2 + lw2) * 4 + t2) * 4 + i2) * 32 + ln2];
        v[cc] = s * recip + bias[nb + col];
    }
    *(float4*)(out + (size_t)ar * N_OUT + nb + c0) = make_float4(v[0], v[1], v[2], v[3]);
}

// ====================== launch ======================
extern "C" void kernel_launch(void* const* d_in, const int* in_sizes, int n_in,
                              void* d_out, int out_size) {
    const float* A    = (const float*)d_in[0];   // [32, 4096]
    const float* W    = (const float*)d_in[1];   // [12288, 4096]
    const float* bias = (const float*)d_in[2];   // [12288]
    float* out        = (float*)d_out;           // [32, 12288]

    cudaFuncSetAttribute(k_gemm, cudaFuncAttributeMaxDynamicSharedMemorySize, DSMEM);

    k_amax<<<1184, 256>>>(W, A);
    k_gemm<<<NTILES, 256, DSMEM>>>(W, bias, out);
}